// round 1
// baseline (speedup 1.0000x reference)
#include <cuda_runtime.h>

// ----------------------------------------------------------------------------
// Problem constants
// ----------------------------------------------------------------------------
#define N_CHR 50000
#define E_CHR 500000
#define N_SLV 30000
#define E_SLV 300000
#define BATCH 256
#define FEAT  64
#define DIM   128
#define HALF  64
#define ENS   3
#define SLOT  ((long)N_CHR * DIM)   // per-ensemble scratch slot (floats)

// ----------------------------------------------------------------------------
// Device scratch (static globals; no allocation anywhere)
// ----------------------------------------------------------------------------
__device__ float g_ax[N_CHR * FEAT];        // aggregated input features (shared across ens)
__device__ float g_bufA[ENS * N_CHR * DIM]; // h0 / a1 / a2 per ensemble
__device__ float g_bufB[ENS * N_CHR * DIM]; // g1 / g2 per ensemble
__device__ float g_rep[ENS * BATCH * HALF]; // pooled representation
__device__ float g_hg[BATCH * 2 * ENS * DIM]; // concatenated head outputs [256,768]
__device__ float g_hg2[BATCH * DIM];        // fc1 output

// ----------------------------------------------------------------------------
// Scatter-add over edges: out[dst] += in[src], F = 2^logF features per node.
// One thread per (edge, feature). blockIdx.z = ensemble (strided buffers).
// ----------------------------------------------------------------------------
__global__ void scatter_add_kernel(const float* __restrict__ in,
                                   float* __restrict__ out,
                                   const int* __restrict__ srci,
                                   const int* __restrict__ dsti,
                                   int E, int logF, long sIn, long sOut)
{
    int idx = blockIdx.x * blockDim.x + threadIdx.x;
    int total = E << logF;
    if (idx >= total) return;
    int e = idx >> logF;
    int f = idx & ((1 << logF) - 1);
    int s = srci[e];
    int d = dsti[e];
    float v = in[blockIdx.z * sIn + ((long)s << logF) + f];
    atomicAdd(&out[blockIdx.z * sOut + ((long)d << logF) + f], v);
}

// ----------------------------------------------------------------------------
// Global add pool with fused relu: rep[batch[n]] += relu(in[n]), F=64.
// ----------------------------------------------------------------------------
__global__ void pool_kernel(const float* __restrict__ in,
                            const int* __restrict__ batchids,
                            float* __restrict__ out,
                            int N, long sIn, long sOut)
{
    int idx = blockIdx.x * blockDim.x + threadIdx.x;
    if (idx >= N * HALF) return;
    int n = idx >> 6;
    int f = idx & 63;
    int b = batchids[n];
    float v = fmaxf(in[blockIdx.z * sIn + (long)n * HALF + f], 0.0f);
    atomicAdd(&out[blockIdx.z * sOut + (long)b * HALF + f], v);
}

// ----------------------------------------------------------------------------
// Register-tiled fp32 GEMM:  C[nrows, BN] = op(A[nrows, K]) @ W[K, BN]
// BM=64 rows per block, BN in {64,128} = full output width, BK=16.
// 256 threads, micro-tile TM=4 x TN=(BN/16). blockIdx.z = ensemble batch with
// independent strides on A / W / C / bias. Optional relu on input and output,
// optional bias.
// ----------------------------------------------------------------------------
template <int BN, int TN>
__global__ void gemm_kernel(const float* __restrict__ A,
                            const float* __restrict__ W,
                            const float* __restrict__ bias,
                            float* __restrict__ C,
                            int nrows, int K, int ldA, int ldC,
                            long sA, long sW, long sC, long sB,
                            int reluIn, int reluOut)
{
    const int BM = 64, BK = 16, TM = 4;
    A += blockIdx.z * sA;
    W += blockIdx.z * sW;
    C += blockIdx.z * sC;
    if (bias) bias += blockIdx.z * sB;

    __shared__ float As[BK][BM + 1];  // pad -> conflict-free stores/loads
    __shared__ float Ws[BK][BN];

    int tid = threadIdx.x;
    int tx = tid & 15;
    int ty = tid >> 4;
    int row0 = blockIdx.x * BM;

    float acc[TM][TN];
#pragma unroll
    for (int i = 0; i < TM; i++)
#pragma unroll
        for (int j = 0; j < TN; j++) acc[i][j] = 0.0f;

    for (int k0 = 0; k0 < K; k0 += BK) {
        // Load A tile (BM x BK), transposed into smem As[k][m]
#pragma unroll
        for (int i = 0; i < (BM * BK) / 256; i++) {
            int t = tid + i * 256;
            int m = t >> 4;
            int k = t & 15;
            int row = row0 + m;
            float v = (row < nrows) ? A[(long)row * ldA + k0 + k] : 0.0f;
            if (reluIn) v = fmaxf(v, 0.0f);
            As[k][m] = v;
        }
        // Load W tile (BK x BN)
#pragma unroll
        for (int i = 0; i < (BN * BK) / 256; i++) {
            int t = tid + i * 256;
            int n, k;
            if (BN == 128) { n = t & 127; k = t >> 7; }
            else           { n = t & 63;  k = t >> 6; }
            Ws[k][n] = W[(long)(k0 + k) * BN + n];
        }
        __syncthreads();

#pragma unroll
        for (int k = 0; k < BK; k++) {
            float ra[TM], rb[TN];
#pragma unroll
            for (int i = 0; i < TM; i++) ra[i] = As[k][ty + i * 16];
#pragma unroll
            for (int j = 0; j < TN; j++) rb[j] = Ws[k][tx + j * 16];
#pragma unroll
            for (int i = 0; i < TM; i++)
#pragma unroll
                for (int j = 0; j < TN; j++)
                    acc[i][j] = fmaf(ra[i], rb[j], acc[i][j]);
        }
        __syncthreads();
    }

    // Epilogue
#pragma unroll
    for (int i = 0; i < TM; i++) {
        int row = row0 + ty + i * 16;
        if (row < nrows) {
#pragma unroll
            for (int j = 0; j < TN; j++) {
                int col = tx + j * 16;
                float v = acc[i][j];
                if (bias) v += bias[col];
                if (reluOut) v = fmaxf(v, 0.0f);
                C[(long)row * ldC + col] = v;
            }
        }
    }
}

// ----------------------------------------------------------------------------
// Final fc2: out[row] = dot(hg2[row,:], W[:,0]) + b[0]   ([256,128]@[128,1])
// ----------------------------------------------------------------------------
__global__ void fc2_kernel(const float* __restrict__ A,
                           const float* __restrict__ W,
                           const float* __restrict__ b,
                           float* __restrict__ out)
{
    int row = blockIdx.x;
    float v = A[row * DIM + threadIdx.x] * W[threadIdx.x];
#pragma unroll
    for (int o = 16; o > 0; o >>= 1) v += __shfl_down_sync(0xffffffffu, v, o);
    __shared__ float s[4];
    if ((threadIdx.x & 31) == 0) s[threadIdx.x >> 5] = v;
    __syncthreads();
    if (threadIdx.x == 0) out[row] = s[0] + s[1] + s[2] + s[3] + b[0];
}

// ----------------------------------------------------------------------------
// Host-side orchestration
// ----------------------------------------------------------------------------
static inline void launch_gemm128(const float* A, const float* W, const float* bias,
                                  float* C, int nrows, int K, int ldA, int ldC,
                                  long sA, long sW, long sC, long sB,
                                  int ri, int ro, int nz)
{
    dim3 g((nrows + 63) / 64, 1, nz);
    gemm_kernel<128, 8><<<g, 256>>>(A, W, bias, C, nrows, K, ldA, ldC, sA, sW, sC, sB, ri, ro);
}

static inline void launch_gemm64(const float* A, const float* W, const float* bias,
                                 float* C, int nrows, int K, int ldA, int ldC,
                                 long sA, long sW, long sC, long sB,
                                 int ri, int ro, int nz)
{
    dim3 g((nrows + 63) / 64, 1, nz);
    gemm_kernel<64, 4><<<g, 256>>>(A, W, bias, C, nrows, K, ldA, ldC, sA, sW, sC, sB, ri, ro);
}

static void run_branch(const float* x, const int* ei, const int* batchids,
                       const float* W0, const float* W1, const float* W2,
                       const float* fcW, const float* fcb,
                       int N, int E, float* hg_base,
                       float* p_ax, float* p_bufA, float* p_bufB, float* p_rep)
{
    const int* src = ei;
    const int* dst = ei + E;

    // Layer 0: aggregate x ONCE (linearity: agg(x@W) == agg(x)@W), 64-wide.
    cudaMemsetAsync(p_ax, 0, (size_t)N * FEAT * sizeof(float));
    {
        int total = E << 6;  // F = 64
        scatter_add_kernel<<<dim3((total + 255) / 256, 1, 1), 256>>>(
            x, p_ax, src, dst, E, 6, 0, 0);
    }
    // h0[e] = relu(ax @ W0[e])   K=64, M=128  (A shared across ensembles: sA=0)
    launch_gemm128(p_ax, W0, nullptr, p_bufA, N, FEAT, FEAT, DIM,
                   0, (long)FEAT * DIM, SLOT, 0, /*ri*/0, /*ro*/1, ENS);

    // Layer 1: g1[e] = h0[e] @ W1[e]; a1[e] = agg(g1[e])  (128-wide)
    launch_gemm128(p_bufA, W1, nullptr, p_bufB, N, DIM, DIM, DIM,
                   SLOT, (long)DIM * DIM, SLOT, 0, 0, 0, ENS);
    for (int e = 0; e < ENS; e++)
        cudaMemsetAsync(p_bufA + e * SLOT, 0, (size_t)N * DIM * sizeof(float));
    {
        int total = E << 7;  // F = 128
        scatter_add_kernel<<<dim3((total + 255) / 256, 1, ENS), 256>>>(
            p_bufB, p_bufA, src, dst, E, 7, SLOT, SLOT);
    }

    // Layer 2: g2[e] = relu(a1[e]) @ W2[e]  (K=128, M=64); a2[e] = agg(g2[e]) (64-wide)
    launch_gemm64(p_bufA, W2, nullptr, p_bufB, N, DIM, DIM, HALF,
                  SLOT, (long)DIM * HALF, SLOT, 0, /*ri*/1, 0, ENS);
    for (int e = 0; e < ENS; e++)
        cudaMemsetAsync(p_bufA + e * SLOT, 0, (size_t)N * HALF * sizeof(float));
    {
        int total = E << 6;  // F = 64
        scatter_add_kernel<<<dim3((total + 255) / 256, 1, ENS), 256>>>(
            p_bufB, p_bufA, src, dst, E, 6, SLOT, SLOT);
    }

    // Pool: rep[e] = segment_sum(relu(a2[e]), batchids)
    cudaMemsetAsync(p_rep, 0, (size_t)ENS * BATCH * HALF * sizeof(float));
    {
        int total = N * HALF;
        pool_kernel<<<dim3((total + 255) / 256, 1, ENS), 256>>>(
            p_bufA, batchids, p_rep, N, SLOT, (long)BATCH * HALF);
    }

    // Head: hg[:, off + e*128 : ...] = relu(rep[e] @ fcW[e] + fcb[e])
    launch_gemm128(p_rep, fcW, fcb, hg_base, BATCH, HALF, HALF, 2 * ENS * DIM,
                   (long)BATCH * HALF, (long)HALF * DIM, DIM, DIM, 0, 1, ENS);
}

extern "C" void kernel_launch(void* const* d_in, const int* in_sizes, int n_in,
                              void* d_out, int out_size)
{
    // Resolve input ordering at runtime: metadata may follow the setup_inputs
    // dict order or the reference() signature order. Disambiguate via sizes:
    // dict order has chr_edge_index (2*500000 = 1,000,000) at slot 2; signature
    // order has chr_W0 (24,576) there.
    int i_chr_x, i_slv_x, i_chr_ei, i_slv_ei, i_chr_b, i_slv_b;
    int i_cW0, i_cW1, i_cW2, i_sW0, i_sW1, i_sW2;
    int i_cfcW, i_cfcB, i_sfcW, i_sfcB, i_fc1W, i_fc1B, i_fc2W, i_fc2B;
    if (in_sizes[2] == 2 * E_CHR) {
        // dict order
        i_chr_x = 0;  i_slv_x = 1;  i_chr_ei = 2; i_slv_ei = 3;
        i_chr_b = 4;  i_slv_b = 5;
        i_cW0 = 6;  i_cW1 = 7;  i_cW2 = 8;
        i_sW0 = 9;  i_sW1 = 10; i_sW2 = 11;
        i_cfcW = 12; i_cfcB = 13; i_sfcW = 14; i_sfcB = 15;
        i_fc1W = 16; i_fc1B = 17; i_fc2W = 18; i_fc2B = 19;
    } else {
        // reference-signature order
        i_chr_x = 0;  i_slv_x = 1;
        i_cW0 = 2;  i_cW1 = 3;  i_cW2 = 4;
        i_sW0 = 5;  i_sW1 = 6;  i_sW2 = 7;
        i_cfcW = 8;  i_cfcB = 9;  i_sfcW = 10; i_sfcB = 11;
        i_fc1W = 12; i_fc1B = 13; i_fc2W = 14; i_fc2B = 15;
        i_chr_ei = 16; i_slv_ei = 17; i_chr_b = 18; i_slv_b = 19;
    }

    const float* chr_x = (const float*)d_in[i_chr_x];
    const float* slv_x = (const float*)d_in[i_slv_x];
    const int* chr_ei = (const int*)d_in[i_chr_ei];
    const int* slv_ei = (const int*)d_in[i_slv_ei];
    const int* chr_bi = (const int*)d_in[i_chr_b];
    const int* slv_bi = (const int*)d_in[i_slv_b];
    const float* cW0 = (const float*)d_in[i_cW0];
    const float* cW1 = (const float*)d_in[i_cW1];
    const float* cW2 = (const float*)d_in[i_cW2];
    const float* sW0 = (const float*)d_in[i_sW0];
    const float* sW1 = (const float*)d_in[i_sW1];
    const float* sW2 = (const float*)d_in[i_sW2];
    const float* cfcW = (const float*)d_in[i_cfcW];
    const float* cfcB = (const float*)d_in[i_cfcB];
    const float* sfcW = (const float*)d_in[i_sfcW];
    const float* sfcB = (const float*)d_in[i_sfcB];
    const float* fc1W = (const float*)d_in[i_fc1W];
    const float* fc1B = (const float*)d_in[i_fc1B];
    const float* fc2W = (const float*)d_in[i_fc2W];
    const float* fc2B = (const float*)d_in[i_fc2B];

    float *p_ax, *p_bufA, *p_bufB, *p_rep, *p_hg, *p_hg2;
    cudaGetSymbolAddress((void**)&p_ax,   g_ax);
    cudaGetSymbolAddress((void**)&p_bufA, g_bufA);
    cudaGetSymbolAddress((void**)&p_bufB, g_bufB);
    cudaGetSymbolAddress((void**)&p_rep,  g_rep);
    cudaGetSymbolAddress((void**)&p_hg,   g_hg);
    cudaGetSymbolAddress((void**)&p_hg2,  g_hg2);

    // chr branch -> hg columns [0, 384)
    run_branch(chr_x, chr_ei, chr_bi, cW0, cW1, cW2, cfcW, cfcB,
               N_CHR, E_CHR, p_hg, p_ax, p_bufA, p_bufB, p_rep);
    // slv branch -> hg columns [384, 768)
    run_branch(slv_x, slv_ei, slv_bi, sW0, sW1, sW2, sfcW, sfcB,
               N_SLV, E_SLV, p_hg + ENS * DIM, p_ax, p_bufA, p_bufB, p_rep);

    // fc1: hg2 = relu(hg @ fc1W + fc1B)   [256,768]@[768,128]
    launch_gemm128(p_hg, fc1W, fc1B, p_hg2, BATCH, 2 * ENS * DIM,
                   2 * ENS * DIM, DIM, 0, 0, 0, 0, 0, 1, 1);

    // fc2: out = hg2 @ fc2W + fc2B   [256,128]@[128,1]
    fc2_kernel<<<BATCH, DIM>>>(p_hg2, fc2W, fc2B, (float*)d_out);
}

// round 2
// speedup vs baseline: 1.8742x; 1.8742x over previous
#include <cuda_runtime.h>

// ----------------------------------------------------------------------------
// Problem constants
// ----------------------------------------------------------------------------
#define N_CHR 50000
#define E_CHR 500000
#define N_SLV 30000
#define E_SLV 300000
#define BATCH 256
#define FEAT  64
#define DIM   128
#define HALF  64
#define ENS   3
#define SLOT  ((long)N_CHR * DIM)   // per-ensemble scratch slot (floats)

// ----------------------------------------------------------------------------
// Device scratch (static globals; no allocation anywhere)
// ----------------------------------------------------------------------------
__device__ float g_ax[N_CHR * FEAT];        // aggregated input features (shared across ens)
__device__ float g_bufA[ENS * N_CHR * DIM]; // h0 / a1 / a2 per ensemble
__device__ float g_bufB[ENS * N_CHR * DIM]; // g1 / g2 per ensemble
__device__ float g_rep[ENS * BATCH * HALF]; // pooled representation
__device__ float g_hg[BATCH * 2 * ENS * DIM]; // concatenated head outputs [256,768]
__device__ float g_hg2[BATCH * DIM];        // fc1 output

// ----------------------------------------------------------------------------
// Vectorized fused-ensemble scatter-add over edges:
//   for z in [0,NZ): out[z][dst[e]][f..f+3] += in[z][src[e]][f..f+3]
// One thread per (edge, 4 features). TPE = F/4 threads per edge; with F=128 a
// full warp covers one edge -> src/dst loads are warp-uniform broadcasts.
// Uses red.global.add.v4.f32 (REDG, no return) to cut issue count 4x.
// ----------------------------------------------------------------------------
template <int LOGTPE, int NZ>
__global__ void scatter_vec_kernel(const float* __restrict__ in,
                                   float* __restrict__ out,
                                   const int* __restrict__ srci,
                                   const int* __restrict__ dsti,
                                   int E, long sIn, long sOut)
{
    const int TPE = 1 << LOGTPE;   // threads per edge
    const int F = TPE * 4;         // features per node
    long tid = (long)blockIdx.x * blockDim.x + threadIdx.x;
    int e = (int)(tid >> LOGTPE);
    if (e >= E) return;
    int f = ((int)tid & (TPE - 1)) << 2;
    long so = (long)srci[e] * F + f;
    long doff = (long)dsti[e] * F + f;
#pragma unroll
    for (int z = 0; z < NZ; z++) {
        float4 v = *(const float4*)(in + z * sIn + so);
        float* p = out + z * sOut + doff;
        asm volatile("red.global.add.v4.f32 [%0], {%1,%2,%3,%4};"
                     :: "l"(p), "f"(v.x), "f"(v.y), "f"(v.z), "f"(v.w)
                     : "memory");
    }
}

// ----------------------------------------------------------------------------
// Global add pool with fused relu, vectorized + ensemble-fused:
//   rep[z][batch[n]][f..f+3] += relu(in[z][n][f..f+3])      (F = 64)
// ----------------------------------------------------------------------------
__global__ void pool_vec_kernel(const float* __restrict__ in,
                                const int* __restrict__ batchids,
                                float* __restrict__ out,
                                int N, long sIn, long sOut)
{
    long tid = (long)blockIdx.x * blockDim.x + threadIdx.x;
    int n = (int)(tid >> 4);       // 16 threads per node (64 feats / 4)
    if (n >= N) return;
    int f = ((int)tid & 15) << 2;
    int b = batchids[n];
    long so = (long)n * HALF + f;
    long doff = (long)b * HALF + f;
#pragma unroll
    for (int z = 0; z < ENS; z++) {
        float4 v = *(const float4*)(in + z * sIn + so);
        v.x = fmaxf(v.x, 0.0f); v.y = fmaxf(v.y, 0.0f);
        v.z = fmaxf(v.z, 0.0f); v.w = fmaxf(v.w, 0.0f);
        float* p = out + z * sOut + doff;
        asm volatile("red.global.add.v4.f32 [%0], {%1,%2,%3,%4};"
                     :: "l"(p), "f"(v.x), "f"(v.y), "f"(v.z), "f"(v.w)
                     : "memory");
    }
}

// ----------------------------------------------------------------------------
// Register-tiled fp32 GEMM:  C[nrows, BN] = op(A[nrows, K]) @ W[K, BN]
// BM=64 rows per block, BN in {64,128} = full output width, BK=16.
// 256 threads, micro-tile TM=4 x TN=(BN/16). blockIdx.z = ensemble batch with
// independent strides on A / W / C / bias. Optional relu on input and output,
// optional bias.
// ----------------------------------------------------------------------------
template <int BN, int TN>
__global__ void gemm_kernel(const float* __restrict__ A,
                            const float* __restrict__ W,
                            const float* __restrict__ bias,
                            float* __restrict__ C,
                            int nrows, int K, int ldA, int ldC,
                            long sA, long sW, long sC, long sB,
                            int reluIn, int reluOut)
{
    const int BM = 64, BK = 16, TM = 4;
    A += blockIdx.z * sA;
    W += blockIdx.z * sW;
    C += blockIdx.z * sC;
    if (bias) bias += blockIdx.z * sB;

    __shared__ float As[BK][BM + 1];  // pad -> conflict-free stores/loads
    __shared__ float Ws[BK][BN];

    int tid = threadIdx.x;
    int tx = tid & 15;
    int ty = tid >> 4;
    int row0 = blockIdx.x * BM;

    float acc[TM][TN];
#pragma unroll
    for (int i = 0; i < TM; i++)
#pragma unroll
        for (int j = 0; j < TN; j++) acc[i][j] = 0.0f;

    for (int k0 = 0; k0 < K; k0 += BK) {
        // Load A tile (BM x BK), transposed into smem As[k][m]
#pragma unroll
        for (int i = 0; i < (BM * BK) / 256; i++) {
            int t = tid + i * 256;
            int m = t >> 4;
            int k = t & 15;
            int row = row0 + m;
            float v = (row < nrows) ? A[(long)row * ldA + k0 + k] : 0.0f;
            if (reluIn) v = fmaxf(v, 0.0f);
            As[k][m] = v;
        }
        // Load W tile (BK x BN)
#pragma unroll
        for (int i = 0; i < (BN * BK) / 256; i++) {
            int t = tid + i * 256;
            int n, k;
            if (BN == 128) { n = t & 127; k = t >> 7; }
            else           { n = t & 63;  k = t >> 6; }
            Ws[k][n] = W[(long)(k0 + k) * BN + n];
        }
        __syncthreads();

#pragma unroll
        for (int k = 0; k < BK; k++) {
            float ra[TM], rb[TN];
#pragma unroll
            for (int i = 0; i < TM; i++) ra[i] = As[k][ty + i * 16];
#pragma unroll
            for (int j = 0; j < TN; j++) rb[j] = Ws[k][tx + j * 16];
#pragma unroll
            for (int i = 0; i < TM; i++)
#pragma unroll
                for (int j = 0; j < TN; j++)
                    acc[i][j] = fmaf(ra[i], rb[j], acc[i][j]);
        }
        __syncthreads();
    }

    // Epilogue
#pragma unroll
    for (int i = 0; i < TM; i++) {
        int row = row0 + ty + i * 16;
        if (row < nrows) {
#pragma unroll
            for (int j = 0; j < TN; j++) {
                int col = tx + j * 16;
                float v = acc[i][j];
                if (bias) v += bias[col];
                if (reluOut) v = fmaxf(v, 0.0f);
                C[(long)row * ldC + col] = v;
            }
        }
    }
}

// ----------------------------------------------------------------------------
// Final fc2: out[row] = dot(hg2[row,:], W[:,0]) + b[0]   ([256,128]@[128,1])
// ----------------------------------------------------------------------------
__global__ void fc2_kernel(const float* __restrict__ A,
                           const float* __restrict__ W,
                           const float* __restrict__ b,
                           float* __restrict__ out)
{
    int row = blockIdx.x;
    float v = A[row * DIM + threadIdx.x] * W[threadIdx.x];
#pragma unroll
    for (int o = 16; o > 0; o >>= 1) v += __shfl_down_sync(0xffffffffu, v, o);
    __shared__ float s[4];
    if ((threadIdx.x & 31) == 0) s[threadIdx.x >> 5] = v;
    __syncthreads();
    if (threadIdx.x == 0) out[row] = s[0] + s[1] + s[2] + s[3] + b[0];
}

// ----------------------------------------------------------------------------
// Host-side orchestration
// ----------------------------------------------------------------------------
static inline void launch_gemm128(const float* A, const float* W, const float* bias,
                                  float* C, int nrows, int K, int ldA, int ldC,
                                  long sA, long sW, long sC, long sB,
                                  int ri, int ro, int nz)
{
    dim3 g((nrows + 63) / 64, 1, nz);
    gemm_kernel<128, 8><<<g, 256>>>(A, W, bias, C, nrows, K, ldA, ldC, sA, sW, sC, sB, ri, ro);
}

static inline void launch_gemm64(const float* A, const float* W, const float* bias,
                                 float* C, int nrows, int K, int ldA, int ldC,
                                 long sA, long sW, long sC, long sB,
                                 int ri, int ro, int nz)
{
    dim3 g((nrows + 63) / 64, 1, nz);
    gemm_kernel<64, 4><<<g, 256>>>(A, W, bias, C, nrows, K, ldA, ldC, sA, sW, sC, sB, ri, ro);
}

static void run_branch(const float* x, const int* ei, const int* batchids,
                       const float* W0, const float* W1, const float* W2,
                       const float* fcW, const float* fcb,
                       int N, int E, float* hg_base,
                       float* p_ax, float* p_bufA, float* p_bufB, float* p_rep)
{
    const int* src = ei;
    const int* dst = ei + E;

    // Layer 0: aggregate x ONCE (linearity: agg(x@W) == agg(x)@W), 64-wide.
    cudaMemsetAsync(p_ax, 0, (size_t)N * FEAT * sizeof(float));
    {
        long total = (long)E * 16;  // F=64 -> 16 threads/edge
        scatter_vec_kernel<4, 1><<<(unsigned)((total + 255) / 256), 256>>>(
            x, p_ax, src, dst, E, 0, 0);
    }
    // h0[e] = relu(ax @ W0[e])   K=64, M=128  (A shared across ensembles: sA=0)
    launch_gemm128(p_ax, W0, nullptr, p_bufA, N, FEAT, FEAT, DIM,
                   0, (long)FEAT * DIM, SLOT, 0, /*ri*/0, /*ro*/1, ENS);

    // Layer 1: g1[e] = h0[e] @ W1[e]; a1[e] = agg(g1[e])  (128-wide)
    launch_gemm128(p_bufA, W1, nullptr, p_bufB, N, DIM, DIM, DIM,
                   SLOT, (long)DIM * DIM, SLOT, 0, 0, 0, ENS);
    for (int e = 0; e < ENS; e++)
        cudaMemsetAsync(p_bufA + e * SLOT, 0, (size_t)N * DIM * sizeof(float));
    {
        long total = (long)E * 32;  // F=128 -> 32 threads/edge
        scatter_vec_kernel<5, ENS><<<(unsigned)((total + 255) / 256), 256>>>(
            p_bufB, p_bufA, src, dst, E, SLOT, SLOT);
    }

    // Layer 2: g2[e] = relu(a1[e]) @ W2[e]  (K=128, M=64); a2[e] = agg(g2[e]) (64-wide)
    launch_gemm64(p_bufA, W2, nullptr, p_bufB, N, DIM, DIM, HALF,
                  SLOT, (long)DIM * HALF, SLOT, 0, /*ri*/1, 0, ENS);
    for (int e = 0; e < ENS; e++)
        cudaMemsetAsync(p_bufA + e * SLOT, 0, (size_t)N * HALF * sizeof(float));
    {
        long total = (long)E * 16;  // F=64
        scatter_vec_kernel<4, ENS><<<(unsigned)((total + 255) / 256), 256>>>(
            p_bufB, p_bufA, src, dst, E, SLOT, SLOT);
    }

    // Pool: rep[e] = segment_sum(relu(a2[e]), batchids)
    cudaMemsetAsync(p_rep, 0, (size_t)ENS * BATCH * HALF * sizeof(float));
    {
        long total = (long)N * 16;
        pool_vec_kernel<<<(unsigned)((total + 255) / 256), 256>>>(
            p_bufA, batchids, p_rep, N, SLOT, (long)BATCH * HALF);
    }

    // Head: hg[:, off + e*128 : ...] = relu(rep[e] @ fcW[e] + fcb[e])
    launch_gemm128(p_rep, fcW, fcb, hg_base, BATCH, HALF, HALF, 2 * ENS * DIM,
                   (long)BATCH * HALF, (long)HALF * DIM, DIM, DIM, 0, 1, ENS);
}

extern "C" void kernel_launch(void* const* d_in, const int* in_sizes, int n_in,
                              void* d_out, int out_size)
{
    // Resolve input ordering at runtime (dict order vs signature order).
    int i_chr_x, i_slv_x, i_chr_ei, i_slv_ei, i_chr_b, i_slv_b;
    int i_cW0, i_cW1, i_cW2, i_sW0, i_sW1, i_sW2;
    int i_cfcW, i_cfcB, i_sfcW, i_sfcB, i_fc1W, i_fc1B, i_fc2W, i_fc2B;
    if (in_sizes[2] == 2 * E_CHR) {
        i_chr_x = 0;  i_slv_x = 1;  i_chr_ei = 2; i_slv_ei = 3;
        i_chr_b = 4;  i_slv_b = 5;
        i_cW0 = 6;  i_cW1 = 7;  i_cW2 = 8;
        i_sW0 = 9;  i_sW1 = 10; i_sW2 = 11;
        i_cfcW = 12; i_cfcB = 13; i_sfcW = 14; i_sfcB = 15;
        i_fc1W = 16; i_fc1B = 17; i_fc2W = 18; i_fc2B = 19;
    } else {
        i_chr_x = 0;  i_slv_x = 1;
        i_cW0 = 2;  i_cW1 = 3;  i_cW2 = 4;
        i_sW0 = 5;  i_sW1 = 6;  i_sW2 = 7;
        i_cfcW = 8;  i_cfcB = 9;  i_sfcW = 10; i_sfcB = 11;
        i_fc1W = 12; i_fc1B = 13; i_fc2W = 14; i_fc2B = 15;
        i_chr_ei = 16; i_slv_ei = 17; i_chr_b = 18; i_slv_b = 19;
    }

    const float* chr_x = (const float*)d_in[i_chr_x];
    const float* slv_x = (const float*)d_in[i_slv_x];
    const int* chr_ei = (const int*)d_in[i_chr_ei];
    const int* slv_ei = (const int*)d_in[i_slv_ei];
    const int* chr_bi = (const int*)d_in[i_chr_b];
    const int* slv_bi = (const int*)d_in[i_slv_b];
    const float* cW0 = (const float*)d_in[i_cW0];
    const float* cW1 = (const float*)d_in[i_cW1];
    const float* cW2 = (const float*)d_in[i_cW2];
    const float* sW0 = (const float*)d_in[i_sW0];
    const float* sW1 = (const float*)d_in[i_sW1];
    const float* sW2 = (const float*)d_in[i_sW2];
    const float* cfcW = (const float*)d_in[i_cfcW];
    const float* cfcB = (const float*)d_in[i_cfcB];
    const float* sfcW = (const float*)d_in[i_sfcW];
    const float* sfcB = (const float*)d_in[i_sfcB];
    const float* fc1W = (const float*)d_in[i_fc1W];
    const float* fc1B = (const float*)d_in[i_fc1B];
    const float* fc2W = (const float*)d_in[i_fc2W];
    const float* fc2B = (const float*)d_in[i_fc2B];

    float *p_ax, *p_bufA, *p_bufB, *p_rep, *p_hg, *p_hg2;
    cudaGetSymbolAddress((void**)&p_ax,   g_ax);
    cudaGetSymbolAddress((void**)&p_bufA, g_bufA);
    cudaGetSymbolAddress((void**)&p_bufB, g_bufB);
    cudaGetSymbolAddress((void**)&p_rep,  g_rep);
    cudaGetSymbolAddress((void**)&p_hg,   g_hg);
    cudaGetSymbolAddress((void**)&p_hg2,  g_hg2);

    // chr branch -> hg columns [0, 384)
    run_branch(chr_x, chr_ei, chr_bi, cW0, cW1, cW2, cfcW, cfcB,
               N_CHR, E_CHR, p_hg, p_ax, p_bufA, p_bufB, p_rep);
    // slv branch -> hg columns [384, 768)
    run_branch(slv_x, slv_ei, slv_bi, sW0, sW1, sW2, sfcW, sfcB,
               N_SLV, E_SLV, p_hg + ENS * DIM, p_ax, p_bufA, p_bufB, p_rep);

    // fc1: hg2 = relu(hg @ fc1W + fc1B)   [256,768]@[768,128]
    launch_gemm128(p_hg, fc1W, fc1B, p_hg2, BATCH, 2 * ENS * DIM,
                   2 * ENS * DIM, DIM, 0, 0, 0, 0, 0, 1, 1);

    // fc2: out = hg2 @ fc2W + fc2B   [256,128]@[128,1]
    fc2_kernel<<<BATCH, DIM>>>(p_hg2, fc2W, fc2B, (float*)d_out);
}